// round 2
// baseline (speedup 1.0000x reference)
#include <cuda_runtime.h>
#include <math.h>

#define B_    32
#define T_    2
#define NT    196
#define D_    768
#define HEADS 12
#define HD    64
#define HT    14
#define WT    14
#define HS    96
#define WS    96
#define NS    (HS*WS)       // 9216
#define NK    (NS+1)        // 9217
#define SMH   (HS-HT+1)     // 83
#define SMW   (WS-WT+1)     // 83

__device__ float g_proto[B_*D_];
__device__ float g_track[B_*NS];
__device__ float g_blur [B_*NS];

// ---------------------------------------------------------------------------
// Kernel A: box-masked pooling -> proto[b, 768]
// One block per b, 256 threads, each thread handles 3 of the 768 dims.
// ---------------------------------------------------------------------------
__global__ void __launch_bounds__(256) proto_kernel(const float* __restrict__ patches,
                                                    const float* __restrict__ annos) {
    int b   = blockIdx.x;
    int tid = threadIdx.x;

    float acc[T_][3];
    float cnt[T_];

#pragma unroll
    for (int t = 0; t < T_; t++) {
        const float* a = annos + (t * B_ + b) * 4;
        float a0 = a[0], a1 = a[1], a2 = a[2], a3 = a[3];
        int x1 = (int)floorf(a0 * (float)WT);
        int y1 = (int)floorf(a1 * (float)HT);
        int x2 = (int)floorf((a0 + a2) * (float)WT);
        int y2 = (int)floorf((a1 + a3) * (float)HT);

        float s0 = 0.f, s1 = 0.f, s2 = 0.f;
        int c = 0;
        const float* base = patches + ((size_t)(t * B_ + b)) * NT * D_;
        for (int p = 0; p < NT; p++) {
            int r  = p / WT;
            int cc = p - r * WT;
            bool m = (r >= y1) && (r < y2) && (cc >= x1) && (cc < x2);
            if (m) {
                c++;
                const float* row = base + (size_t)p * D_;
                s0 += row[tid];
                s1 += row[tid + 256];
                s2 += row[tid + 512];
            }
        }
        acc[t][0] = s0; acc[t][1] = s1; acc[t][2] = s2;
        cnt[t] = (float)c;
    }

#pragma unroll
    for (int i = 0; i < 3; i++) {
        float v = 0.5f * (acc[0][i] / (cnt[0] + 1e-6f) + acc[1][i] / (cnt[1] + 1e-6f));
        g_proto[b * D_ + tid + i * 256] = v;
    }
}

// ---------------------------------------------------------------------------
// Kernel B: attn + head-mean -> track[b, 9216].  The HBM-bound stage.
// Warp per n (4 n's per warp iter). Lane layout: hl = lane>>4 (head parity),
// d4 = lane&15 (float4 slot). Each warp-load covers 2x256B contiguous.
// Proto held in 6 float4 registers per lane (fixed across n).
// ---------------------------------------------------------------------------
__global__ void __launch_bounds__(256) attn_kernel(const float* __restrict__ skey) {
    int b    = blockIdx.y;
    int warp = threadIdx.x >> 5;
    int lane = threadIdx.x & 31;
    int hl   = lane >> 4;     // 0 or 1
    int d4   = lane & 15;     // float4 index within head

    float4 pr[6];
#pragma unroll
    for (int j = 0; j < 6; j++) {
        int h = 2 * j + hl;
        pr[j] = *(const float4*)(g_proto + b * D_ + h * HD + d4 * 4);
    }

    int n0 = blockIdx.x * 32 + warp * 4;   // this warp's 4 n-values
    const float* kb = skey + ((size_t)b * HEADS) * (size_t)NK * HD;

    float acc0 = 0.f, acc1 = 0.f, acc2 = 0.f, acc3 = 0.f;
#pragma unroll
    for (int j = 0; j < 6; j++) {
        int h = 2 * j + hl;
        const float4* p = (const float4*)(kb + ((size_t)h * NK + (size_t)(n0 + 1)) * HD) + d4;
        float4 k0 = p[0 * (HD / 4)];
        float4 k1 = p[1 * (HD / 4)];
        float4 k2 = p[2 * (HD / 4)];
        float4 k3 = p[3 * (HD / 4)];
        acc0 += k0.x * pr[j].x + k0.y * pr[j].y + k0.z * pr[j].z + k0.w * pr[j].w;
        acc1 += k1.x * pr[j].x + k1.y * pr[j].y + k1.z * pr[j].z + k1.w * pr[j].w;
        acc2 += k2.x * pr[j].x + k2.y * pr[j].y + k2.z * pr[j].z + k2.w * pr[j].w;
        acc3 += k3.x * pr[j].x + k3.y * pr[j].y + k3.z * pr[j].z + k3.w * pr[j].w;
    }

    const float scale = 0.125f / 12.0f;   // hd^-0.5 / heads
    float v0 = acc0, v1 = acc1, v2 = acc2, v3 = acc3;
#pragma unroll
    for (int off = 16; off; off >>= 1) {
        v0 += __shfl_xor_sync(0xffffffffu, v0, off);
        v1 += __shfl_xor_sync(0xffffffffu, v1, off);
        v2 += __shfl_xor_sync(0xffffffffu, v2, off);
        v3 += __shfl_xor_sync(0xffffffffu, v3, off);
    }
    if (lane == 0) {
        float* tr = g_track + b * NS + n0;
        tr[0] = v0 * scale;
        tr[1] = v1 * scale;
        tr[2] = v2 * scale;
        tr[3] = v3 * scale;
    }
}

// ---------------------------------------------------------------------------
// Kernel C1: vertical 5-tap blur with reflect padding, g_track -> g_blur
// ---------------------------------------------------------------------------
__device__ __forceinline__ int reflect_idx(int i, int n) {
    if (i < 0)  return -i;
    if (i >= n) return 2 * n - 2 - i;
    return i;
}

__global__ void __launch_bounds__(256) blurv_kernel() {
    int b = blockIdx.y;
    int i = blockIdx.x * 256 + threadIdx.x;
    if (i >= NS) return;
    int y = i / WS, x = i - y * WS;

    float k1 = expf(-1.0f / 2.42f);
    float k2 = expf(-4.0f / 2.42f);
    float s  = 1.0f + 2.0f * k1 + 2.0f * k2;
    float w0 = 1.0f / s, w1 = k1 / s, w2 = k2 / s;

    const float* tr = g_track + b * NS;
    float vm2 = tr[reflect_idx(y - 2, HS) * WS + x];
    float vm1 = tr[reflect_idx(y - 1, HS) * WS + x];
    float v0  = tr[y * WS + x];
    float vp1 = tr[reflect_idx(y + 1, HS) * WS + x];
    float vp2 = tr[reflect_idx(y + 2, HS) * WS + x];
    g_blur[b * NS + i] = w2 * vm2 + w1 * vm1 + w0 * v0 + w1 * vp1 + w2 * vp2;
}

// ---------------------------------------------------------------------------
// Kernel C2: per-batch: horizontal blur -> softmax -> prob out ->
//            integral image -> 14x14 window sums -> argmax -> scalar outs.
// One block per b, 256 threads, everything in static smem (~39KB).
// Output layout (float32): [best_x(32) | best_y(32) | win_w(32) | win_h(32)
//                          | confidence(32) | prob(32*9216)]
// ---------------------------------------------------------------------------
__global__ void __launch_bounds__(256) post_kernel(float* __restrict__ out) {
    __shared__ float sA[NS];
    __shared__ float red[256];
    __shared__ int   redi[256];

    int b   = blockIdx.x;
    int tid = threadIdx.x;

    float k1 = expf(-1.0f / 2.42f);
    float k2 = expf(-4.0f / 2.42f);
    float s  = 1.0f + 2.0f * k1 + 2.0f * k2;
    float w0 = 1.0f / s, w1 = k1 / s, w2 = k2 / s;

    const float* bl = g_blur + b * NS;
    // horizontal blur
    for (int i = tid; i < NS; i += 256) {
        int y = i / WS, x = i - y * WS;
        const float* row = bl + y * WS;
        float vm2 = row[reflect_idx(x - 2, WS)];
        float vm1 = row[reflect_idx(x - 1, WS)];
        float v0  = row[x];
        float vp1 = row[reflect_idx(x + 1, WS)];
        float vp2 = row[reflect_idx(x + 2, WS)];
        sA[i] = w2 * vm2 + w1 * vm1 + w0 * v0 + w1 * vp1 + w2 * vp2;
    }
    __syncthreads();

    // softmax over 9216
    float m = -3.402823e38f;
    for (int i = tid; i < NS; i += 256) m = fmaxf(m, sA[i]);
    red[tid] = m; __syncthreads();
    for (int off = 128; off; off >>= 1) {
        if (tid < off) red[tid] = fmaxf(red[tid], red[tid + off]);
        __syncthreads();
    }
    m = red[0]; __syncthreads();

    float sum = 0.f;
    for (int i = tid; i < NS; i += 256) { float e = expf(sA[i] - m); sA[i] = e; sum += e; }
    red[tid] = sum; __syncthreads();
    for (int off = 128; off; off >>= 1) {
        if (tid < off) red[tid] += red[tid + off];
        __syncthreads();
    }
    float inv = 1.0f / red[0]; __syncthreads();

    float* probOut = out + 5 * B_ + (size_t)b * NS;
    for (int i = tid; i < NS; i += 256) { float p = sA[i] * inv; sA[i] = p; probOut[i] = p; }
    __syncthreads();

    // integral image: row cumsum then column cumsum (matches jnp order)
    if (tid < HS) {
        float c = 0.f;
        float* r = sA + tid * WS;
        for (int x = 0; x < WS; x++) { c += r[x]; r[x] = c; }
    }
    __syncthreads();
    if (tid < WS) {
        float c = 0.f;
        for (int y = 0; y < HS; y++) { c += sA[y * WS + tid]; sA[y * WS + tid] = c; }
    }
    __syncthreads();

    // 14x14 window sums over 83x83 positions, first-occurrence argmax
    float bv = -3.402823e38f;
    int   bi = 0x7fffffff;
    for (int i = tid; i < SMH * SMW; i += 256) {
        int y = i / SMW, x = i - y * SMW;
        float Dv = sA[(y + HT - 1) * WS + (x + WT - 1)];
        float Bv = (y > 0)          ? sA[(y - 1) * WS + (x + WT - 1)] : 0.0f;
        float Cv = (x > 0)          ? sA[(y + HT - 1) * WS + (x - 1)] : 0.0f;
        float Av = (y > 0 && x > 0) ? sA[(y - 1) * WS + (x - 1)]      : 0.0f;
        float v = Dv - Bv - Cv + Av;
        if (v > bv || (v == bv && i < bi)) { bv = v; bi = i; }
    }
    red[tid] = bv; redi[tid] = bi; __syncthreads();
    for (int off = 128; off; off >>= 1) {
        if (tid < off) {
            float ov = red[tid + off]; int oi = redi[tid + off];
            if (ov > red[tid] || (ov == red[tid] && oi < redi[tid])) {
                red[tid] = ov; redi[tid] = oi;
            }
        }
        __syncthreads();
    }
    if (tid == 0) {
        int idx = redi[0];
        out[0 * B_ + b] = (float)(idx % SMW);   // best_x
        out[1 * B_ + b] = (float)(idx / SMW);   // best_y
        out[2 * B_ + b] = (float)WT;            // win_w
        out[3 * B_ + b] = (float)HT;            // win_h
        out[4 * B_ + b] = red[0];               // confidence
    }
}

// ---------------------------------------------------------------------------
extern "C" void kernel_launch(void* const* d_in, const int* in_sizes, int n_in,
                              void* d_out, int out_size) {
    const float* patches = (const float*)d_in[0];
    const float* annos   = (const float*)d_in[1];
    const float* skey    = (const float*)d_in[2];
    float* out = (float*)d_out;

    proto_kernel<<<B_, 256>>>(patches, annos);

    dim3 gAttn(NS / 32, B_);          // 288 x 32; each block: 8 warps x 4 n = 32 n
    attn_kernel<<<gAttn, 256>>>(skey);

    dim3 gBlur((NS + 255) / 256, B_); // 36 x 32
    blurv_kernel<<<gBlur, 256>>>();

    post_kernel<<<B_, 256>>>(out);
}

// round 8
// speedup vs baseline: 1.0923x; 1.0923x over previous
#include <cuda_runtime.h>
#include <math.h>

#define B_    32
#define T_    2
#define NT    196
#define D_    768
#define HEADS 12
#define HD    64
#define HT    14
#define WT    14
#define HS    96
#define WS    96
#define NS    (HS*WS)       // 9216
#define NK    (NS+1)        // 9217
#define SMH   (HS-HT+1)     // 83
#define SMW   (WS-WT+1)     // 83
#define NPW   8             // n-values per warp in attn

__device__ float g_proto[B_*D_];
__device__ float g_track[B_*NS];

// ---------------------------------------------------------------------------
// Kernel A: box-masked pooling -> proto[b, 768].
// EXACT R2 numerics: conditional adds, division-form normalize, T-avg here.
// ---------------------------------------------------------------------------
__global__ void __launch_bounds__(256) proto_kernel(const float* __restrict__ patches,
                                                    const float* __restrict__ annos) {
    int b   = blockIdx.x;
    int tid = threadIdx.x;

    float acc[T_][3];
    float cnt[T_];

#pragma unroll
    for (int t = 0; t < T_; t++) {
        const float* a = annos + (t * B_ + b) * 4;
        float a0 = a[0], a1 = a[1], a2 = a[2], a3 = a[3];
        int x1 = (int)floorf(a0 * (float)WT);
        int y1 = (int)floorf(a1 * (float)HT);
        int x2 = (int)floorf((a0 + a2) * (float)WT);
        int y2 = (int)floorf((a1 + a3) * (float)HT);

        float s0 = 0.f, s1 = 0.f, s2 = 0.f;
        int c = 0;
        const float* base = patches + ((size_t)(t * B_ + b)) * NT * D_;
        for (int p = 0; p < NT; p++) {
            int r  = p / WT;
            int cc = p - r * WT;
            bool m = (r >= y1) && (r < y2) && (cc >= x1) && (cc < x2);
            if (m) {
                c++;
                const float* row = base + (size_t)p * D_;
                s0 += row[tid];
                s1 += row[tid + 256];
                s2 += row[tid + 512];
            }
        }
        acc[t][0] = s0; acc[t][1] = s1; acc[t][2] = s2;
        cnt[t] = (float)c;
    }

#pragma unroll
    for (int i = 0; i < 3; i++) {
        float v = 0.5f * (acc[0][i] / (cnt[0] + 1e-6f) + acc[1][i] / (cnt[1] + 1e-6f));
        g_proto[b * D_ + tid + i * 256] = v;
    }
}

// ---------------------------------------------------------------------------
// Kernel B: attn + head-mean -> track. HBM-bound (906 MB stream).
// NPW=8 n per warp + streaming loads. Per-output math bit-identical to R2:
// same j-order FMA chain, same shuffle reduction order.
// ---------------------------------------------------------------------------
__global__ void __launch_bounds__(256) attn_kernel(const float* __restrict__ skey) {
    int b    = blockIdx.y;
    int warp = threadIdx.x >> 5;
    int lane = threadIdx.x & 31;
    int hl   = lane >> 4;     // 0 or 1
    int d4   = lane & 15;     // float4 index within head

    float4 pr[6];
#pragma unroll
    for (int j = 0; j < 6; j++) {
        int h = 2 * j + hl;
        pr[j] = *(const float4*)(g_proto + b * D_ + h * HD + d4 * 4);
    }

    int n0 = blockIdx.x * (8 * NPW) + warp * NPW;
    const float* kb = skey + ((size_t)b * HEADS) * (size_t)NK * HD;

    float acc[NPW];
#pragma unroll
    for (int r = 0; r < NPW; r++) acc[r] = 0.f;

#pragma unroll
    for (int j = 0; j < 6; j++) {
        int h = 2 * j + hl;
        const float4* p = (const float4*)(kb + ((size_t)h * NK + (size_t)(n0 + 1)) * HD) + d4;
#pragma unroll
        for (int r = 0; r < NPW; r++) {
            float4 k = __ldcs(p + r * (HD / 4));
            acc[r] += k.x * pr[j].x + k.y * pr[j].y + k.z * pr[j].z + k.w * pr[j].w;
        }
    }

    const float scale = 0.125f / 12.0f;   // hd^-0.5 / heads
#pragma unroll
    for (int r = 0; r < NPW; r++) {
#pragma unroll
        for (int off = 16; off; off >>= 1)
            acc[r] += __shfl_xor_sync(0xffffffffu, acc[r], off);
    }
    if (lane == 0) {
        float4 o0 = make_float4(acc[0] * scale, acc[1] * scale, acc[2] * scale, acc[3] * scale);
        float4 o1 = make_float4(acc[4] * scale, acc[5] * scale, acc[6] * scale, acc[7] * scale);
        float4* tr = (float4*)(g_track + b * NS + n0);
        tr[0] = o0;
        tr[1] = o1;
    }
}

// ---------------------------------------------------------------------------
// Kernel C: per-batch post, EXACT R2 numerics (256 threads, smem trees,
// exact expf, serial cumsums, same tie-break). Vertical blur fused in front
// via second smem array (bit-identical values to R2's g_blur, no DRAM trip).
// ---------------------------------------------------------------------------
__device__ __forceinline__ int reflect_idx(int i, int n) {
    if (i < 0)  return -i;
    if (i >= n) return 2 * n - 2 - i;
    return i;
}

__global__ void __launch_bounds__(256) post_kernel(float* __restrict__ out) {
    __shared__ float sB[NS];   // vertical-blur result (== R2's g_blur)
    __shared__ float sA[NS];
    __shared__ float red[256];
    __shared__ int   redi[256];

    int b   = blockIdx.x;
    int tid = threadIdx.x;

    float k1 = expf(-1.0f / 2.42f);
    float k2 = expf(-4.0f / 2.42f);
    float s  = 1.0f + 2.0f * k1 + 2.0f * k2;
    float w0 = 1.0f / s, w1 = k1 / s, w2 = k2 / s;

    // vertical blur: g_track -> sB (same expression as R2's blurv_kernel)
    const float* tr = g_track + b * NS;
    for (int i = tid; i < NS; i += 256) {
        int y = i / WS, x = i - y * WS;
        float vm2 = tr[reflect_idx(y - 2, HS) * WS + x];
        float vm1 = tr[reflect_idx(y - 1, HS) * WS + x];
        float v0  = tr[y * WS + x];
        float vp1 = tr[reflect_idx(y + 1, HS) * WS + x];
        float vp2 = tr[reflect_idx(y + 2, HS) * WS + x];
        sB[i] = w2 * vm2 + w1 * vm1 + w0 * v0 + w1 * vp1 + w2 * vp2;
    }
    __syncthreads();

    // horizontal blur: sB -> sA
    for (int i = tid; i < NS; i += 256) {
        int y = i / WS, x = i - y * WS;
        const float* row = sB + y * WS;
        float vm2 = row[reflect_idx(x - 2, WS)];
        float vm1 = row[reflect_idx(x - 1, WS)];
        float v0  = row[x];
        float vp1 = row[reflect_idx(x + 1, WS)];
        float vp2 = row[reflect_idx(x + 2, WS)];
        sA[i] = w2 * vm2 + w1 * vm1 + w0 * v0 + w1 * vp1 + w2 * vp2;
    }
    __syncthreads();

    // softmax over 9216 (R2 reduction structure)
    float m = -3.402823e38f;
    for (int i = tid; i < NS; i += 256) m = fmaxf(m, sA[i]);
    red[tid] = m; __syncthreads();
    for (int off = 128; off; off >>= 1) {
        if (tid < off) red[tid] = fmaxf(red[tid], red[tid + off]);
        __syncthreads();
    }
    m = red[0]; __syncthreads();

    float sum = 0.f;
    for (int i = tid; i < NS; i += 256) { float e = expf(sA[i] - m); sA[i] = e; sum += e; }
    red[tid] = sum; __syncthreads();
    for (int off = 128; off; off >>= 1) {
        if (tid < off) red[tid] += red[tid + off];
        __syncthreads();
    }
    float inv = 1.0f / red[0]; __syncthreads();

    float* probOut = out + 5 * B_ + (size_t)b * NS;
    for (int i = tid; i < NS; i += 256) { float p = sA[i] * inv; sA[i] = p; probOut[i] = p; }
    __syncthreads();

    // integral image: row cumsum then column cumsum (matches jnp order)
    if (tid < HS) {
        float c = 0.f;
        float* r = sA + tid * WS;
        for (int x = 0; x < WS; x++) { c += r[x]; r[x] = c; }
    }
    __syncthreads();
    if (tid < WS) {
        float c = 0.f;
        for (int y = 0; y < HS; y++) { c += sA[y * WS + tid]; sA[y * WS + tid] = c; }
    }
    __syncthreads();

    // 14x14 window sums over 83x83 positions, first-occurrence argmax
    float bv = -3.402823e38f;
    int   bi = 0x7fffffff;
    for (int i = tid; i < SMH * SMW; i += 256) {
        int y = i / SMW, x = i - y * SMW;
        float Dv = sA[(y + HT - 1) * WS + (x + WT - 1)];
        float Bv = (y > 0)          ? sA[(y - 1) * WS + (x + WT - 1)] : 0.0f;
        float Cv = (x > 0)          ? sA[(y + HT - 1) * WS + (x - 1)] : 0.0f;
        float Av = (y > 0 && x > 0) ? sA[(y - 1) * WS + (x - 1)]      : 0.0f;
        float v = Dv - Bv - Cv + Av;
        if (v > bv || (v == bv && i < bi)) { bv = v; bi = i; }
    }
    red[tid] = bv; redi[tid] = bi; __syncthreads();
    for (int off = 128; off; off >>= 1) {
        if (tid < off) {
            float ov = red[tid + off]; int oi = redi[tid + off];
            if (ov > red[tid] || (ov == red[tid] && oi < redi[tid])) {
                red[tid] = ov; redi[tid] = oi;
            }
        }
        __syncthreads();
    }
    if (tid == 0) {
        int idx = redi[0];
        out[0 * B_ + b] = (float)(idx % SMW);   // best_x
        out[1 * B_ + b] = (float)(idx / SMW);   // best_y
        out[2 * B_ + b] = (float)WT;            // win_w
        out[3 * B_ + b] = (float)HT;            // win_h
        out[4 * B_ + b] = red[0];               // confidence
    }
}

// ---------------------------------------------------------------------------
extern "C" void kernel_launch(void* const* d_in, const int* in_sizes, int n_in,
                              void* d_out, int out_size) {
    const float* patches = (const float*)d_in[0];
    const float* annos   = (const float*)d_in[1];
    const float* skey    = (const float*)d_in[2];
    float* out = (float*)d_out;

    proto_kernel<<<B_, 256>>>(patches, annos);

    dim3 gAttn(NS / (8 * NPW), B_);   // 144 x 32
    attn_kernel<<<gAttn, 256>>>(skey);

    post_kernel<<<B_, 256>>>(out);
}

// round 9
// speedup vs baseline: 1.0929x; 1.0005x over previous
#include <cuda_runtime.h>
#include <math.h>

#define B_    32
#define T_    2
#define NT    196
#define D_    768
#define HEADS 12
#define HD    64
#define HT    14
#define WT    14
#define HS    96
#define WS    96
#define NS    (HS*WS)       // 9216
#define NK    (NS+1)        // 9217
#define SMH   (HS-HT+1)     // 83
#define SMW   (WS-WT+1)     // 83
#define NPW   8             // n-values per warp in attn
#define DCH   4             // dim-chunks in proto grid
#define DPB   (D_/DCH)      // 192 threads per proto block

__device__ float g_acc[T_][B_][D_];   // per-template masked sums (pre-division)
__device__ float g_cnt[T_][B_];       // per-template counts
__device__ float g_track[B_*NS];

// ---------------------------------------------------------------------------
// Kernel A: box-masked pooling sums. Grid (B, T, DCH), DPB threads.
// Mask-multiply accumulate: bit-identical to the conditional-add order
// (adding +0.0f preserves the accumulator), but loads are unconditional ->
// full streaming MLP across 256 blocks instead of 32 latency-bound blocks.
// Division-form normalize + T-average moved verbatim into attn preload.
// ---------------------------------------------------------------------------
__global__ void __launch_bounds__(DPB) proto_kernel(const float* __restrict__ patches,
                                                    const float* __restrict__ annos) {
    int b = blockIdx.x, t = blockIdx.y;
    int d = blockIdx.z * DPB + threadIdx.x;

    const float* a = annos + (t * B_ + b) * 4;
    float a0 = a[0], a1 = a[1], a2 = a[2], a3 = a[3];
    int x1 = (int)floorf(a0 * (float)WT);
    int y1 = (int)floorf(a1 * (float)HT);
    int x2 = (int)floorf((a0 + a2) * (float)WT);
    int y2 = (int)floorf((a1 + a3) * (float)HT);

    const float* base = patches + ((size_t)(t * B_ + b)) * NT * D_ + d;
    float s = 0.f;
    int c = 0;
#pragma unroll 7
    for (int p = 0; p < NT; p++) {
        int r  = p / WT;
        int cc = p - r * WT;
        bool in = (r >= y1) && (r < y2) && (cc >= x1) && (cc < x2);
        float m = in ? 1.0f : 0.0f;
        c += in ? 1 : 0;
        s += m * base[(size_t)p * D_];
    }
    g_acc[t][b][d] = s;
    if (blockIdx.z == 0 && threadIdx.x == 0) g_cnt[t][b] = (float)c;
}

// ---------------------------------------------------------------------------
// Kernel B: attn + head-mean -> track. HBM-bound (906 MB stream, ~7.2 TB/s).
// Preload does the EXACT R2 combine: 0.5f*(acc0/(cnt0+1e-6) + acc1/(cnt1+1e-6))
// (same ops on same bits as computing it in proto and storing).
// ---------------------------------------------------------------------------
__global__ void __launch_bounds__(256) attn_kernel(const float* __restrict__ skey) {
    int b    = blockIdx.y;
    int warp = threadIdx.x >> 5;
    int lane = threadIdx.x & 31;
    int hl   = lane >> 4;     // 0 or 1
    int d4   = lane & 15;     // float4 index within head

    float c0 = g_cnt[0][b] + 1e-6f;
    float c1 = g_cnt[1][b] + 1e-6f;

    float4 pr[6];
#pragma unroll
    for (int j = 0; j < 6; j++) {
        int h = 2 * j + hl;
        float4 q0 = *(const float4*)(&g_acc[0][b][h * HD + d4 * 4]);
        float4 q1 = *(const float4*)(&g_acc[1][b][h * HD + d4 * 4]);
        pr[j].x = 0.5f * (q0.x / c0 + q1.x / c1);
        pr[j].y = 0.5f * (q0.y / c0 + q1.y / c1);
        pr[j].z = 0.5f * (q0.z / c0 + q1.z / c1);
        pr[j].w = 0.5f * (q0.w / c0 + q1.w / c1);
    }

    int n0 = blockIdx.x * (8 * NPW) + warp * NPW;
    const float* kb = skey + ((size_t)b * HEADS) * (size_t)NK * HD;

    float acc[NPW];
#pragma unroll
    for (int r = 0; r < NPW; r++) acc[r] = 0.f;

#pragma unroll
    for (int j = 0; j < 6; j++) {
        int h = 2 * j + hl;
        const float4* p = (const float4*)(kb + ((size_t)h * NK + (size_t)(n0 + 1)) * HD) + d4;
#pragma unroll
        for (int r = 0; r < NPW; r++) {
            float4 k = __ldcs(p + r * (HD / 4));
            acc[r] += k.x * pr[j].x + k.y * pr[j].y + k.z * pr[j].z + k.w * pr[j].w;
        }
    }

    const float scale = 0.125f / 12.0f;   // hd^-0.5 / heads
#pragma unroll
    for (int r = 0; r < NPW; r++) {
#pragma unroll
        for (int off = 16; off; off >>= 1)
            acc[r] += __shfl_xor_sync(0xffffffffu, acc[r], off);
    }
    if (lane == 0) {
        float4 o0 = make_float4(acc[0] * scale, acc[1] * scale, acc[2] * scale, acc[3] * scale);
        float4 o1 = make_float4(acc[4] * scale, acc[5] * scale, acc[6] * scale, acc[7] * scale);
        float4* tr = (float4*)(g_track + b * NS + n0);
        tr[0] = o0;
        tr[1] = o1;
    }
}

// ---------------------------------------------------------------------------
// Kernel C: per-batch post, EXACT R2 numerics (256 threads, smem trees,
// exact expf, serial cumsums, same tie-break). Vertical blur fused in front
// via second smem array (bit-identical values, no DRAM trip).
// ---------------------------------------------------------------------------
__device__ __forceinline__ int reflect_idx(int i, int n) {
    if (i < 0)  return -i;
    if (i >= n) return 2 * n - 2 - i;
    return i;
}

__global__ void __launch_bounds__(256) post_kernel(float* __restrict__ out) {
    __shared__ float sB[NS];   // vertical-blur result
    __shared__ float sA[NS];
    __shared__ float red[256];
    __shared__ int   redi[256];

    int b   = blockIdx.x;
    int tid = threadIdx.x;

    float k1 = expf(-1.0f / 2.42f);
    float k2 = expf(-4.0f / 2.42f);
    float s  = 1.0f + 2.0f * k1 + 2.0f * k2;
    float w0 = 1.0f / s, w1 = k1 / s, w2 = k2 / s;

    // vertical blur: g_track -> sB
    const float* tr = g_track + b * NS;
    for (int i = tid; i < NS; i += 256) {
        int y = i / WS, x = i - y * WS;
        float vm2 = tr[reflect_idx(y - 2, HS) * WS + x];
        float vm1 = tr[reflect_idx(y - 1, HS) * WS + x];
        float v0  = tr[y * WS + x];
        float vp1 = tr[reflect_idx(y + 1, HS) * WS + x];
        float vp2 = tr[reflect_idx(y + 2, HS) * WS + x];
        sB[i] = w2 * vm2 + w1 * vm1 + w0 * v0 + w1 * vp1 + w2 * vp2;
    }
    __syncthreads();

    // horizontal blur: sB -> sA
    for (int i = tid; i < NS; i += 256) {
        int y = i / WS, x = i - y * WS;
        const float* row = sB + y * WS;
        float vm2 = row[reflect_idx(x - 2, WS)];
        float vm1 = row[reflect_idx(x - 1, WS)];
        float v0  = row[x];
        float vp1 = row[reflect_idx(x + 1, WS)];
        float vp2 = row[reflect_idx(x + 2, WS)];
        sA[i] = w2 * vm2 + w1 * vm1 + w0 * v0 + w1 * vp1 + w2 * vp2;
    }
    __syncthreads();

    // softmax over 9216
    float m = -3.402823e38f;
    for (int i = tid; i < NS; i += 256) m = fmaxf(m, sA[i]);
    red[tid] = m; __syncthreads();
    for (int off = 128; off; off >>= 1) {
        if (tid < off) red[tid] = fmaxf(red[tid], red[tid + off]);
        __syncthreads();
    }
    m = red[0]; __syncthreads();

    float sum = 0.f;
    for (int i = tid; i < NS; i += 256) { float e = expf(sA[i] - m); sA[i] = e; sum += e; }
    red[tid] = sum; __syncthreads();
    for (int off = 128; off; off >>= 1) {
        if (tid < off) red[tid] += red[tid + off];
        __syncthreads();
    }
    float inv = 1.0f / red[0]; __syncthreads();

    float* probOut = out + 5 * B_ + (size_t)b * NS;
    for (int i = tid; i < NS; i += 256) { float p = sA[i] * inv; sA[i] = p; probOut[i] = p; }
    __syncthreads();

    // integral image: row cumsum then column cumsum
    if (tid < HS) {
        float c = 0.f;
        float* r = sA + tid * WS;
        for (int x = 0; x < WS; x++) { c += r[x]; r[x] = c; }
    }
    __syncthreads();
    if (tid < WS) {
        float c = 0.f;
        for (int y = 0; y < HS; y++) { c += sA[y * WS + tid]; sA[y * WS + tid] = c; }
    }
    __syncthreads();

    // 14x14 window sums over 83x83 positions, first-occurrence argmax
    float bv = -3.402823e38f;
    int   bi = 0x7fffffff;
    for (int i = tid; i < SMH * SMW; i += 256) {
        int y = i / SMW, x = i - y * SMW;
        float Dv = sA[(y + HT - 1) * WS + (x + WT - 1)];
        float Bv = (y > 0)          ? sA[(y - 1) * WS + (x + WT - 1)] : 0.0f;
        float Cv = (x > 0)          ? sA[(y + HT - 1) * WS + (x - 1)] : 0.0f;
        float Av = (y > 0 && x > 0) ? sA[(y - 1) * WS + (x - 1)]      : 0.0f;
        float v = Dv - Bv - Cv + Av;
        if (v > bv || (v == bv && i < bi)) { bv = v; bi = i; }
    }
    red[tid] = bv; redi[tid] = bi; __syncthreads();
    for (int off = 128; off; off >>= 1) {
        if (tid < off) {
            float ov = red[tid + off]; int oi = redi[tid + off];
            if (ov > red[tid] || (ov == red[tid] && oi < redi[tid])) {
                red[tid] = ov; redi[tid] = oi;
            }
        }
        __syncthreads();
    }
    if (tid == 0) {
        int idx = redi[0];
        out[0 * B_ + b] = (float)(idx % SMW);   // best_x
        out[1 * B_ + b] = (float)(idx / SMW);   // best_y
        out[2 * B_ + b] = (float)WT;            // win_w
        out[3 * B_ + b] = (float)HT;            // win_h
        out[4 * B_ + b] = red[0];               // confidence
    }
}

// ---------------------------------------------------------------------------
extern "C" void kernel_launch(void* const* d_in, const int* in_sizes, int n_in,
                              void* d_out, int out_size) {
    const float* patches = (const float*)d_in[0];
    const float* annos   = (const float*)d_in[1];
    const float* skey    = (const float*)d_in[2];
    float* out = (float*)d_out;

    proto_kernel<<<dim3(B_, T_, DCH), DPB>>>(patches, annos);

    dim3 gAttn(NS / (8 * NPW), B_);   // 144 x 32
    attn_kernel<<<gAttn, 256>>>(skey);

    post_kernel<<<B_, 256>>>(out);
}

// round 11
// speedup vs baseline: 1.1279x; 1.0321x over previous
#include <cuda_runtime.h>
#include <math.h>

#define B_    32
#define T_    2
#define NT    196
#define D_    768
#define HEADS 12
#define HD    64
#define HT    14
#define WT    14
#define HS    96
#define WS    96
#define NS    (HS*WS)       // 9216
#define NK    (NS+1)        // 9217
#define SMH   (HS-HT+1)     // 83
#define SMW   (WS-WT+1)     // 83
#define NPW   8             // n-values per warp in attn
#define DCH   4             // dim-chunks in proto grid
#define DPB   (D_/DCH)      // 192 threads per proto block

__device__ float g_acc[T_][B_][D_];   // per-template masked sums (pre-division)
__device__ float g_cnt[T_][B_];       // per-template counts
__device__ float g_track[B_*NS];

// ---------------------------------------------------------------------------
// Kernel A: box-masked pooling sums. Grid (B, T, DCH), DPB threads.
// FULLY UNROLLED nested r/cc loops: same p=0..195 accumulation order
// (bit-identical), but all indices/offsets are compile-time constants ->
// no per-iter div/mod ALU chain, and ptxas batches large groups of
// independent immediate-offset LDGs (MLP ~24+ vs 7) to cover DRAM latency.
// Division-form normalize + T-average stay in attn preload (verbatim R2 math).
// ---------------------------------------------------------------------------
__global__ void __launch_bounds__(DPB) proto_kernel(const float* __restrict__ patches,
                                                    const float* __restrict__ annos) {
    int b = blockIdx.x, t = blockIdx.y;
    int d = blockIdx.z * DPB + threadIdx.x;

    const float* a = annos + (t * B_ + b) * 4;
    float a0 = a[0], a1 = a[1], a2 = a[2], a3 = a[3];
    int x1 = (int)floorf(a0 * (float)WT);
    int y1 = (int)floorf(a1 * (float)HT);
    int x2 = (int)floorf((a0 + a2) * (float)WT);
    int y2 = (int)floorf((a1 + a3) * (float)HT);

    const float* base = patches + ((size_t)(t * B_ + b)) * NT * D_ + d;
    float s = 0.f;
    int c = 0;
#pragma unroll
    for (int r = 0; r < HT; r++) {
        bool inr = (r >= y1) && (r < y2);
#pragma unroll
        for (int cc = 0; cc < WT; cc++) {
            bool in = inr && (cc >= x1) && (cc < x2);
            float m = in ? 1.0f : 0.0f;
            c += in ? 1 : 0;
            s += m * base[(size_t)(r * WT + cc) * D_];
        }
    }
    g_acc[t][b][d] = s;
    if (blockIdx.z == 0 && threadIdx.x == 0) g_cnt[t][b] = (float)c;
}

// ---------------------------------------------------------------------------
// Kernel B: attn + head-mean -> track. HBM-bound (906 MB stream, ~6.5 TB/s).
// Preload does the EXACT R2 combine: 0.5f*(acc0/(cnt0+1e-6) + acc1/(cnt1+1e-6)).
// UNCHANGED from R9 (passing, bit-exact).
// ---------------------------------------------------------------------------
__global__ void __launch_bounds__(256) attn_kernel(const float* __restrict__ skey) {
    int b    = blockIdx.y;
    int warp = threadIdx.x >> 5;
    int lane = threadIdx.x & 31;
    int hl   = lane >> 4;     // 0 or 1
    int d4   = lane & 15;     // float4 index within head

    float c0 = g_cnt[0][b] + 1e-6f;
    float c1 = g_cnt[1][b] + 1e-6f;

    float4 pr[6];
#pragma unroll
    for (int j = 0; j < 6; j++) {
        int h = 2 * j + hl;
        float4 q0 = *(const float4*)(&g_acc[0][b][h * HD + d4 * 4]);
        float4 q1 = *(const float4*)(&g_acc[1][b][h * HD + d4 * 4]);
        pr[j].x = 0.5f * (q0.x / c0 + q1.x / c1);
        pr[j].y = 0.5f * (q0.y / c0 + q1.y / c1);
        pr[j].z = 0.5f * (q0.z / c0 + q1.z / c1);
        pr[j].w = 0.5f * (q0.w / c0 + q1.w / c1);
    }

    int n0 = blockIdx.x * (8 * NPW) + warp * NPW;
    const float* kb = skey + ((size_t)b * HEADS) * (size_t)NK * HD;

    float acc[NPW];
#pragma unroll
    for (int r = 0; r < NPW; r++) acc[r] = 0.f;

#pragma unroll
    for (int j = 0; j < 6; j++) {
        int h = 2 * j + hl;
        const float4* p = (const float4*)(kb + ((size_t)h * NK + (size_t)(n0 + 1)) * HD) + d4;
#pragma unroll
        for (int r = 0; r < NPW; r++) {
            float4 k = __ldcs(p + r * (HD / 4));
            acc[r] += k.x * pr[j].x + k.y * pr[j].y + k.z * pr[j].z + k.w * pr[j].w;
        }
    }

    const float scale = 0.125f / 12.0f;   // hd^-0.5 / heads
#pragma unroll
    for (int r = 0; r < NPW; r++) {
#pragma unroll
        for (int off = 16; off; off >>= 1)
            acc[r] += __shfl_xor_sync(0xffffffffu, acc[r], off);
    }
    if (lane == 0) {
        float4 o0 = make_float4(acc[0] * scale, acc[1] * scale, acc[2] * scale, acc[3] * scale);
        float4 o1 = make_float4(acc[4] * scale, acc[5] * scale, acc[6] * scale, acc[7] * scale);
        float4* tr = (float4*)(g_track + b * NS + n0);
        tr[0] = o0;
        tr[1] = o1;
    }
}

// ---------------------------------------------------------------------------
// Kernel C: per-batch post, EXACT R2 numerics (256 threads, smem trees,
// exact expf, serial cumsums, same tie-break). Vertical blur fused in front
// via second smem array. UNCHANGED from R9 (passing, bit-exact).
// ---------------------------------------------------------------------------
__device__ __forceinline__ int reflect_idx(int i, int n) {
    if (i < 0)  return -i;
    if (i >= n) return 2 * n - 2 - i;
    return i;
}

__global__ void __launch_bounds__(256) post_kernel(float* __restrict__ out) {
    __shared__ float sB[NS];   // vertical-blur result
    __shared__ float sA[NS];
    __shared__ float red[256];
    __shared__ int   redi[256];

    int b   = blockIdx.x;
    int tid = threadIdx.x;

    float k1 = expf(-1.0f / 2.42f);
    float k2 = expf(-4.0f / 2.42f);
    float s  = 1.0f + 2.0f * k1 + 2.0f * k2;
    float w0 = 1.0f / s, w1 = k1 / s, w2 = k2 / s;

    // vertical blur: g_track -> sB
    const float* tr = g_track + b * NS;
    for (int i = tid; i < NS; i += 256) {
        int y = i / WS, x = i - y * WS;
        float vm2 = tr[reflect_idx(y - 2, HS) * WS + x];
        float vm1 = tr[reflect_idx(y - 1, HS) * WS + x];
        float v0  = tr[y * WS + x];
        float vp1 = tr[reflect_idx(y + 1, HS) * WS + x];
        float vp2 = tr[reflect_idx(y + 2, HS) * WS + x];
        sB[i] = w2 * vm2 + w1 * vm1 + w0 * v0 + w1 * vp1 + w2 * vp2;
    }
    __syncthreads();

    // horizontal blur: sB -> sA
    for (int i = tid; i < NS; i += 256) {
        int y = i / WS, x = i - y * WS;
        const float* row = sB + y * WS;
        float vm2 = row[reflect_idx(x - 2, WS)];
        float vm1 = row[reflect_idx(x - 1, WS)];
        float v0  = row[x];
        float vp1 = row[reflect_idx(x + 1, WS)];
        float vp2 = row[reflect_idx(x + 2, WS)];
        sA[i] = w2 * vm2 + w1 * vm1 + w0 * v0 + w1 * vp1 + w2 * vp2;
    }
    __syncthreads();

    // softmax over 9216
    float m = -3.402823e38f;
    for (int i = tid; i < NS; i += 256) m = fmaxf(m, sA[i]);
    red[tid] = m; __syncthreads();
    for (int off = 128; off; off >>= 1) {
        if (tid < off) red[tid] = fmaxf(red[tid], red[tid + off]);
        __syncthreads();
    }
    m = red[0]; __syncthreads();

    float sum = 0.f;
    for (int i = tid; i < NS; i += 256) { float e = expf(sA[i] - m); sA[i] = e; sum += e; }
    red[tid] = sum; __syncthreads();
    for (int off = 128; off; off >>= 1) {
        if (tid < off) red[tid] += red[tid + off];
        __syncthreads();
    }
    float inv = 1.0f / red[0]; __syncthreads();

    float* probOut = out + 5 * B_ + (size_t)b * NS;
    for (int i = tid; i < NS; i += 256) { float p = sA[i] * inv; sA[i] = p; probOut[i] = p; }
    __syncthreads();

    // integral image: row cumsum then column cumsum
    if (tid < HS) {
        float c = 0.f;
        float* r = sA + tid * WS;
        for (int x = 0; x < WS; x++) { c += r[x]; r[x] = c; }
    }
    __syncthreads();
    if (tid < WS) {
        float c = 0.f;
        for (int y = 0; y < HS; y++) { c += sA[y * WS + tid]; sA[y * WS + tid] = c; }
    }
    __syncthreads();

    // 14x14 window sums over 83x83 positions, first-occurrence argmax
    float bv = -3.402823e38f;
    int   bi = 0x7fffffff;
    for (int i = tid; i < SMH * SMW; i += 256) {
        int y = i / SMW, x = i - y * SMW;
        float Dv = sA[(y + HT - 1) * WS + (x + WT - 1)];
        float Bv = (y > 0)          ? sA[(y - 1) * WS + (x + WT - 1)] : 0.0f;
        float Cv = (x > 0)          ? sA[(y + HT - 1) * WS + (x - 1)] : 0.0f;
        float Av = (y > 0 && x > 0) ? sA[(y - 1) * WS + (x - 1)]      : 0.0f;
        float v = Dv - Bv - Cv + Av;
        if (v > bv || (v == bv && i < bi)) { bv = v; bi = i; }
    }
    red[tid] = bv; redi[tid] = bi; __syncthreads();
    for (int off = 128; off; off >>= 1) {
        if (tid < off) {
            float ov = red[tid + off]; int oi = redi[tid + off];
            if (ov > red[tid] || (ov == red[tid] && oi < redi[tid])) {
                red[tid] = ov; redi[tid] = oi;
            }
        }
        __syncthreads();
    }
    if (tid == 0) {
        int idx = redi[0];
        out[0 * B_ + b] = (float)(idx % SMW);   // best_x
        out[1 * B_ + b] = (float)(idx / SMW);   // best_y
        out[2 * B_ + b] = (float)WT;            // win_w
        out[3 * B_ + b] = (float)HT;            // win_h
        out[4 * B_ + b] = red[0];               // confidence
    }
}

// ---------------------------------------------------------------------------
extern "C" void kernel_launch(void* const* d_in, const int* in_sizes, int n_in,
                              void* d_out, int out_size) {
    const float* patches = (const float*)d_in[0];
    const float* annos   = (const float*)d_in[1];
    const float* skey    = (const float*)d_in[2];
    float* out = (float*)d_out;

    proto_kernel<<<dim3(B_, T_, DCH), DPB>>>(patches, annos);

    dim3 gAttn(NS / (8 * NPW), B_);   // 144 x 32
    attn_kernel<<<gAttn, 256>>>(skey);

    post_kernel<<<B_, 256>>>(out);
}

// round 13
// speedup vs baseline: 1.1307x; 1.0025x over previous
#include <cuda_runtime.h>
#include <math.h>

#define B_    32
#define T_    2
#define NT    196
#define D_    768
#define HEADS 12
#define HD    64
#define HT    14
#define WT    14
#define HS    96
#define WS    96
#define NS    (HS*WS)       // 9216
#define NK    (NS+1)        // 9217
#define SMH   (HS-HT+1)     // 83
#define SMW   (WS-WT+1)     // 83
#define NPW   16            // n-values per warp in attn
#define D4    (D_/4)        // 192 float4-dims
#define DCH   6             // dim-chunks in proto grid
#define DPB   (D4/DCH)      // 32 threads per proto block (1 warp)

__device__ float g_acc[T_][B_][D_];   // per-template masked sums (pre-division)
__device__ float g_cnt[T_][B_];       // per-template counts
__device__ float g_track[B_*NS];

// ---------------------------------------------------------------------------
// Kernel A: box-masked pooling sums, FLOAT4 per thread.
// Per-dim accumulation order is still p=0..195 with +0.0f for masked-out
// patches -> bit-identical to R11. 4x bytes in flight per load slot; 1-warp
// blocks (384 of them) with no reg cap so ptxas batches ~40 LDG.128s.
// ---------------------------------------------------------------------------
__global__ void __launch_bounds__(DPB) proto_kernel(const float* __restrict__ patches,
                                                    const float* __restrict__ annos) {
    int b = blockIdx.x, t = blockIdx.y;
    int d4i = blockIdx.z * DPB + threadIdx.x;   // float4 index 0..191

    const float* a = annos + (t * B_ + b) * 4;
    float a0 = a[0], a1 = a[1], a2 = a[2], a3 = a[3];
    int x1 = (int)floorf(a0 * (float)WT);
    int y1 = (int)floorf(a1 * (float)HT);
    int x2 = (int)floorf((a0 + a2) * (float)WT);
    int y2 = (int)floorf((a1 + a3) * (float)HT);

    const float4* base = (const float4*)(patches + ((size_t)(t * B_ + b)) * NT * D_) + d4i;
    float4 s = make_float4(0.f, 0.f, 0.f, 0.f);
    int c = 0;
#pragma unroll
    for (int r = 0; r < HT; r++) {
        bool inr = (r >= y1) && (r < y2);
#pragma unroll
        for (int cc = 0; cc < WT; cc++) {
            bool in = inr && (cc >= x1) && (cc < x2);
            float m = in ? 1.0f : 0.0f;
            c += in ? 1 : 0;
            float4 v = base[(size_t)(r * WT + cc) * D4];
            s.x += m * v.x;
            s.y += m * v.y;
            s.z += m * v.z;
            s.w += m * v.w;
        }
    }
    *((float4*)&g_acc[t][b][0] + d4i) = s;
    if (blockIdx.z == 0 && threadIdx.x == 0) g_cnt[t][b] = (float)c;
}

// ---------------------------------------------------------------------------
// Kernel B: attn + head-mean -> track. HBM-bound (906 MB stream).
// NPW=16: per-output FMA chain and shuffle order unchanged (bit-identical to
// R11); fewer reduction phases per byte, 4KB contiguous per (j,h) segment.
// Preload does the EXACT R2 combine: 0.5f*(acc0/(cnt0+1e-6)+acc1/(cnt1+1e-6)).
// ---------------------------------------------------------------------------
__global__ void __launch_bounds__(256) attn_kernel(const float* __restrict__ skey) {
    int b    = blockIdx.y;
    int warp = threadIdx.x >> 5;
    int lane = threadIdx.x & 31;
    int hl   = lane >> 4;     // 0 or 1
    int d4   = lane & 15;     // float4 index within head

    float c0 = g_cnt[0][b] + 1e-6f;
    float c1 = g_cnt[1][b] + 1e-6f;

    float4 pr[6];
#pragma unroll
    for (int j = 0; j < 6; j++) {
        int h = 2 * j + hl;
        float4 q0 = *(const float4*)(&g_acc[0][b][h * HD + d4 * 4]);
        float4 q1 = *(const float4*)(&g_acc[1][b][h * HD + d4 * 4]);
        pr[j].x = 0.5f * (q0.x / c0 + q1.x / c1);
        pr[j].y = 0.5f * (q0.y / c0 + q1.y / c1);
        pr[j].z = 0.5f * (q0.z / c0 + q1.z / c1);
        pr[j].w = 0.5f * (q0.w / c0 + q1.w / c1);
    }

    int n0 = blockIdx.x * (8 * NPW) + warp * NPW;
    const float* kb = skey + ((size_t)b * HEADS) * (size_t)NK * HD;

    float acc[NPW];
#pragma unroll
    for (int r = 0; r < NPW; r++) acc[r] = 0.f;

#pragma unroll
    for (int j = 0; j < 6; j++) {
        int h = 2 * j + hl;
        const float4* p = (const float4*)(kb + ((size_t)h * NK + (size_t)(n0 + 1)) * HD) + d4;
#pragma unroll
        for (int r = 0; r < NPW; r++) {
            float4 k = __ldcs(p + r * (HD / 4));
            acc[r] += k.x * pr[j].x + k.y * pr[j].y + k.z * pr[j].z + k.w * pr[j].w;
        }
    }

    const float scale = 0.125f / 12.0f;   // hd^-0.5 / heads
#pragma unroll
    for (int r = 0; r < NPW; r++) {
#pragma unroll
        for (int off = 16; off; off >>= 1)
            acc[r] += __shfl_xor_sync(0xffffffffu, acc[r], off);
    }
    if (lane == 0) {
        float4* tr = (float4*)(g_track + b * NS + n0);
#pragma unroll
        for (int q = 0; q < NPW / 4; q++) {
            tr[q] = make_float4(acc[4 * q + 0] * scale, acc[4 * q + 1] * scale,
                                acc[4 * q + 2] * scale, acc[4 * q + 3] * scale);
        }
    }
}

// ---------------------------------------------------------------------------
// Kernel C: per-batch post, EXACT R2 numerics. UNCHANGED from R11.
// ---------------------------------------------------------------------------
__device__ __forceinline__ int reflect_idx(int i, int n) {
    if (i < 0)  return -i;
    if (i >= n) return 2 * n - 2 - i;
    return i;
}

__global__ void __launch_bounds__(256) post_kernel(float* __restrict__ out) {
    __shared__ float sB[NS];   // vertical-blur result
    __shared__ float sA[NS];
    __shared__ float red[256];
    __shared__ int   redi[256];

    int b   = blockIdx.x;
    int tid = threadIdx.x;

    float k1 = expf(-1.0f / 2.42f);
    float k2 = expf(-4.0f / 2.42f);
    float s  = 1.0f + 2.0f * k1 + 2.0f * k2;
    float w0 = 1.0f / s, w1 = k1 / s, w2 = k2 / s;

    // vertical blur: g_track -> sB
    const float* tr = g_track + b * NS;
    for (int i = tid; i < NS; i += 256) {
        int y = i / WS, x = i - y * WS;
        float vm2 = tr[reflect_idx(y - 2, HS) * WS + x];
        float vm1 = tr[reflect_idx(y - 1, HS) * WS + x];
        float v0  = tr[y * WS + x];
        float vp1 = tr[reflect_idx(y + 1, HS) * WS + x];
        float vp2 = tr[reflect_idx(y + 2, HS) * WS + x];
        sB[i] = w2 * vm2 + w1 * vm1 + w0 * v0 + w1 * vp1 + w2 * vp2;
    }
    __syncthreads();

    // horizontal blur: sB -> sA
    for (int i = tid; i < NS; i += 256) {
        int y = i / WS, x = i - y * WS;
        const float* row = sB + y * WS;
        float vm2 = row[reflect_idx(x - 2, WS)];
        float vm1 = row[reflect_idx(x - 1, WS)];
        float v0  = row[x];
        float vp1 = row[reflect_idx(x + 1, WS)];
        float vp2 = row[reflect_idx(x + 2, WS)];
        sA[i] = w2 * vm2 + w1 * vm1 + w0 * v0 + w1 * vp1 + w2 * vp2;
    }
    __syncthreads();

    // softmax over 9216
    float m = -3.402823e38f;
    for (int i = tid; i < NS; i += 256) m = fmaxf(m, sA[i]);
    red[tid] = m; __syncthreads();
    for (int off = 128; off; off >>= 1) {
        if (tid < off) red[tid] = fmaxf(red[tid], red[tid + off]);
        __syncthreads();
    }
    m = red[0]; __syncthreads();

    float sum = 0.f;
    for (int i = tid; i < NS; i += 256) { float e = expf(sA[i] - m); sA[i] = e; sum += e; }
    red[tid] = sum; __syncthreads();
    for (int off = 128; off; off >>= 1) {
        if (tid < off) red[tid] += red[tid + off];
        __syncthreads();
    }
    float inv = 1.0f / red[0]; __syncthreads();

    float* probOut = out + 5 * B_ + (size_t)b * NS;
    for (int i = tid; i < NS; i += 256) { float p = sA[i] * inv; sA[i] = p; probOut[i] = p; }
    __syncthreads();

    // integral image: row cumsum then column cumsum
    if (tid < HS) {
        float c = 0.f;
        float* r = sA + tid * WS;
        for (int x = 0; x < WS; x++) { c += r[x]; r[x] = c; }
    }
    __syncthreads();
    if (tid < WS) {
        float c = 0.f;
        for (int y = 0; y < HS; y++) { c += sA[y * WS + tid]; sA[y * WS + tid] = c; }
    }
    __syncthreads();

    // 14x14 window sums over 83x83 positions, first-occurrence argmax
    float bv = -3.402823e38f;
    int   bi = 0x7fffffff;
    for (int i = tid; i < SMH * SMW; i += 256) {
        int y = i / SMW, x = i - y * SMW;
        float Dv = sA[(y + HT - 1) * WS + (x + WT - 1)];
        float Bv = (y > 0)          ? sA[(y - 1) * WS + (x + WT - 1)] : 0.0f;
        float Cv = (x > 0)          ? sA[(y + HT - 1) * WS + (x - 1)] : 0.0f;
        float Av = (y > 0 && x > 0) ? sA[(y - 1) * WS + (x - 1)]      : 0.0f;
        float v = Dv - Bv - Cv + Av;
        if (v > bv || (v == bv && i < bi)) { bv = v; bi = i; }
    }
    red[tid] = bv; redi[tid] = bi; __syncthreads();
    for (int off = 128; off; off >>= 1) {
        if (tid < off) {
            float ov = red[tid + off]; int oi = redi[tid + off];
            if (ov > red[tid] || (ov == red[tid] && oi < redi[tid])) {
                red[tid] = ov; redi[tid] = oi;
            }
        }
        __syncthreads();
    }
    if (tid == 0) {
        int idx = redi[0];
        out[0 * B_ + b] = (float)(idx % SMW);   // best_x
        out[1 * B_ + b] = (float)(idx / SMW);   // best_y
        out[2 * B_ + b] = (float)WT;            // win_w
        out[3 * B_ + b] = (float)HT;            // win_h
        out[4 * B_ + b] = red[0];               // confidence
    }
}

// ---------------------------------------------------------------------------
extern "C" void kernel_launch(void* const* d_in, const int* in_sizes, int n_in,
                              void* d_out, int out_size) {
    const float* patches = (const float*)d_in[0];
    const float* annos   = (const float*)d_in[1];
    const float* skey    = (const float*)d_in[2];
    float* out = (float*)d_out;

    proto_kernel<<<dim3(B_, T_, DCH), DPB>>>(patches, annos);

    dim3 gAttn(NS / (8 * NPW), B_);   // 72 x 32
    attn_kernel<<<gAttn, 256>>>(skey);

    post_kernel<<<B_, 256>>>(out);
}

// round 14
// speedup vs baseline: 1.1784x; 1.0421x over previous
#include <cuda_runtime.h>
#include <math.h>

#define B_    32
#define T_    2
#define NT    196
#define D_    768
#define HEADS 12
#define HD    64
#define HT    14
#define WT    14
#define HS    96
#define WS    96
#define NS    (HS*WS)       // 9216
#define NK    (NS+1)        // 9217
#define SMH   (HS-HT+1)     // 83
#define SMW   (WS-WT+1)     // 83
#define NPW   16            // n-values per warp in attn
#define AWRP  4             // warps per attn block
#define DCH   8             // dim-chunks in proto grid
#define DPB   (D_/DCH)      // 96 threads per proto block

__device__ float g_acc[T_][B_][D_];   // per-template masked sums (pre-division)
__device__ float g_cnt[T_][B_];       // per-template counts
__device__ float g_track[B_*NS];

// ---------------------------------------------------------------------------
// Kernel A: box-masked pooling sums. SCALAR per thread (R11 mapping: thread
// count beats load width for this stream — R13's float4 collapsed occupancy).
// Grid (B, T, 8) = 512 blocks x 96 threads for finer SM load balance.
// Fully unrolled r/cc loops, same p=0..195 order -> bit-identical.
// ---------------------------------------------------------------------------
__global__ void __launch_bounds__(DPB) proto_kernel(const float* __restrict__ patches,
                                                    const float* __restrict__ annos) {
    int b = blockIdx.x, t = blockIdx.y;
    int d = blockIdx.z * DPB + threadIdx.x;

    const float* a = annos + (t * B_ + b) * 4;
    float a0 = a[0], a1 = a[1], a2 = a[2], a3 = a[3];
    int x1 = (int)floorf(a0 * (float)WT);
    int y1 = (int)floorf(a1 * (float)HT);
    int x2 = (int)floorf((a0 + a2) * (float)WT);
    int y2 = (int)floorf((a1 + a3) * (float)HT);

    const float* base = patches + ((size_t)(t * B_ + b)) * NT * D_ + d;
    float s = 0.f;
    int c = 0;
#pragma unroll
    for (int r = 0; r < HT; r++) {
        bool inr = (r >= y1) && (r < y2);
#pragma unroll
        for (int cc = 0; cc < WT; cc++) {
            bool in = inr && (cc >= x1) && (cc < x2);
            float m = in ? 1.0f : 0.0f;
            c += in ? 1 : 0;
            s += m * base[(size_t)(r * WT + cc) * D_];
        }
    }
    g_acc[t][b][d] = s;
    if (blockIdx.z == 0 && threadIdx.x == 0) g_cnt[t][b] = (float)c;
}

// ---------------------------------------------------------------------------
// Kernel B: attn + head-mean -> track. HBM-bound (906 MB stream).
// 128-thread blocks (4 warps) x NPW=16: per-warp load/FMA/shuffle sequence
// identical to R13 (bit-exact); more, smaller blocks smooth wave quantization.
// Preload does the EXACT R2 combine: 0.5f*(acc0/(cnt0+1e-6)+acc1/(cnt1+1e-6)).
// ---------------------------------------------------------------------------
__global__ void __launch_bounds__(32*AWRP) attn_kernel(const float* __restrict__ skey) {
    int b    = blockIdx.y;
    int warp = threadIdx.x >> 5;
    int lane = threadIdx.x & 31;
    int hl   = lane >> 4;     // 0 or 1
    int d4   = lane & 15;     // float4 index within head

    float c0 = g_cnt[0][b] + 1e-6f;
    float c1 = g_cnt[1][b] + 1e-6f;

    float4 pr[6];
#pragma unroll
    for (int j = 0; j < 6; j++) {
        int h = 2 * j + hl;
        float4 q0 = *(const float4*)(&g_acc[0][b][h * HD + d4 * 4]);
        float4 q1 = *(const float4*)(&g_acc[1][b][h * HD + d4 * 4]);
        pr[j].x = 0.5f * (q0.x / c0 + q1.x / c1);
        pr[j].y = 0.5f * (q0.y / c0 + q1.y / c1);
        pr[j].z = 0.5f * (q0.z / c0 + q1.z / c1);
        pr[j].w = 0.5f * (q0.w / c0 + q1.w / c1);
    }

    int n0 = blockIdx.x * (AWRP * NPW) + warp * NPW;
    const float* kb = skey + ((size_t)b * HEADS) * (size_t)NK * HD;

    float acc[NPW];
#pragma unroll
    for (int r = 0; r < NPW; r++) acc[r] = 0.f;

#pragma unroll
    for (int j = 0; j < 6; j++) {
        int h = 2 * j + hl;
        const float4* p = (const float4*)(kb + ((size_t)h * NK + (size_t)(n0 + 1)) * HD) + d4;
#pragma unroll
        for (int r = 0; r < NPW; r++) {
            float4 k = __ldcs(p + r * (HD / 4));
            acc[r] += k.x * pr[j].x + k.y * pr[j].y + k.z * pr[j].z + k.w * pr[j].w;
        }
    }

    const float scale = 0.125f / 12.0f;   // hd^-0.5 / heads
#pragma unroll
    for (int r = 0; r < NPW; r++) {
#pragma unroll
        for (int off = 16; off; off >>= 1)
            acc[r] += __shfl_xor_sync(0xffffffffu, acc[r], off);
    }
    if (lane == 0) {
        float4* tr = (float4*)(g_track + b * NS + n0);
#pragma unroll
        for (int q = 0; q < NPW / 4; q++) {
            tr[q] = make_float4(acc[4 * q + 0] * scale, acc[4 * q + 1] * scale,
                                acc[4 * q + 2] * scale, acc[4 * q + 3] * scale);
        }
    }
}

// ---------------------------------------------------------------------------
// Kernel C: per-batch post, EXACT R2 numerics. UNCHANGED (passing, bit-exact).
// ---------------------------------------------------------------------------
__device__ __forceinline__ int reflect_idx(int i, int n) {
    if (i < 0)  return -i;
    if (i >= n) return 2 * n - 2 - i;
    return i;
}

__global__ void __launch_bounds__(256) post_kernel(float* __restrict__ out) {
    __shared__ float sB[NS];   // vertical-blur result
    __shared__ float sA[NS];
    __shared__ float red[256];
    __shared__ int   redi[256];

    int b   = blockIdx.x;
    int tid = threadIdx.x;

    float k1 = expf(-1.0f / 2.42f);
    float k2 = expf(-4.0f / 2.42f);
    float s  = 1.0f + 2.0f * k1 + 2.0f * k2;
    float w0 = 1.0f / s, w1 = k1 / s, w2 = k2 / s;

    // vertical blur: g_track -> sB
    const float* tr = g_track + b * NS;
    for (int i = tid; i < NS; i += 256) {
        int y = i / WS, x = i - y * WS;
        float vm2 = tr[reflect_idx(y - 2, HS) * WS + x];
        float vm1 = tr[reflect_idx(y - 1, HS) * WS + x];
        float v0  = tr[y * WS + x];
        float vp1 = tr[reflect_idx(y + 1, HS) * WS + x];
        float vp2 = tr[reflect_idx(y + 2, HS) * WS + x];
        sB[i] = w2 * vm2 + w1 * vm1 + w0 * v0 + w1 * vp1 + w2 * vp2;
    }
    __syncthreads();

    // horizontal blur: sB -> sA
    for (int i = tid; i < NS; i += 256) {
        int y = i / WS, x = i - y * WS;
        const float* row = sB + y * WS;
        float vm2 = row[reflect_idx(x - 2, WS)];
        float vm1 = row[reflect_idx(x - 1, WS)];
        float v0  = row[x];
        float vp1 = row[reflect_idx(x + 1, WS)];
        float vp2 = row[reflect_idx(x + 2, WS)];
        sA[i] = w2 * vm2 + w1 * vm1 + w0 * v0 + w1 * vp1 + w2 * vp2;
    }
    __syncthreads();

    // softmax over 9216
    float m = -3.402823e38f;
    for (int i = tid; i < NS; i += 256) m = fmaxf(m, sA[i]);
    red[tid] = m; __syncthreads();
    for (int off = 128; off; off >>= 1) {
        if (tid < off) red[tid] = fmaxf(red[tid], red[tid + off]);
        __syncthreads();
    }
    m = red[0]; __syncthreads();

    float sum = 0.f;
    for (int i = tid; i < NS; i += 256) { float e = expf(sA[i] - m); sA[i] = e; sum += e; }
    red[tid] = sum; __syncthreads();
    for (int off = 128; off; off >>= 1) {
        if (tid < off) red[tid] += red[tid + off];
        __syncthreads();
    }
    float inv = 1.0f / red[0]; __syncthreads();

    float* probOut = out + 5 * B_ + (size_t)b * NS;
    for (int i = tid; i < NS; i += 256) { float p = sA[i] * inv; sA[i] = p; probOut[i] = p; }
    __syncthreads();

    // integral image: row cumsum then column cumsum
    if (tid < HS) {
        float c = 0.f;
        float* r = sA + tid * WS;
        for (int x = 0; x < WS; x++) { c += r[x]; r[x] = c; }
    }
    __syncthreads();
    if (tid < WS) {
        float c = 0.f;
        for (int y = 0; y < HS; y++) { c += sA[y * WS + tid]; sA[y * WS + tid] = c; }
    }
    __syncthreads();

    // 14x14 window sums over 83x83 positions, first-occurrence argmax
    float bv = -3.402823e38f;
    int   bi = 0x7fffffff;
    for (int i = tid; i < SMH * SMW; i += 256) {
        int y = i / SMW, x = i - y * SMW;
        float Dv = sA[(y + HT - 1) * WS + (x + WT - 1)];
        float Bv = (y > 0)          ? sA[(y - 1) * WS + (x + WT - 1)] : 0.0f;
        float Cv = (x > 0)          ? sA[(y + HT - 1) * WS + (x - 1)] : 0.0f;
        float Av = (y > 0 && x > 0) ? sA[(y - 1) * WS + (x - 1)]      : 0.0f;
        float v = Dv - Bv - Cv + Av;
        if (v > bv || (v == bv && i < bi)) { bv = v; bi = i; }
    }
    red[tid] = bv; redi[tid] = bi; __syncthreads();
    for (int off = 128; off; off >>= 1) {
        if (tid < off) {
            float ov = red[tid + off]; int oi = redi[tid + off];
            if (ov > red[tid] || (ov == red[tid] && oi < redi[tid])) {
                red[tid] = ov; redi[tid] = oi;
            }
        }
        __syncthreads();
    }
    if (tid == 0) {
        int idx = redi[0];
        out[0 * B_ + b] = (float)(idx % SMW);   // best_x
        out[1 * B_ + b] = (float)(idx / SMW);   // best_y
        out[2 * B_ + b] = (float)WT;            // win_w
        out[3 * B_ + b] = (float)HT;            // win_h
        out[4 * B_ + b] = red[0];               // confidence
    }
}

// ---------------------------------------------------------------------------
extern "C" void kernel_launch(void* const* d_in, const int* in_sizes, int n_in,
                              void* d_out, int out_size) {
    const float* patches = (const float*)d_in[0];
    const float* annos   = (const float*)d_in[1];
    const float* skey    = (const float*)d_in[2];
    float* out = (float*)d_out;

    proto_kernel<<<dim3(B_, T_, DCH), DPB>>>(patches, annos);

    dim3 gAttn(NS / (AWRP * NPW), B_);   // 144 x 32
    attn_kernel<<<gAttn, 32 * AWRP>>>(skey);

    post_kernel<<<B_, 256>>>(out);
}

// round 15
// speedup vs baseline: 1.2004x; 1.0187x over previous
#include <cuda_runtime.h>
#include <math.h>

#define B_    32
#define T_    2
#define NT    196
#define D_    768
#define HEADS 12
#define HD    64
#define HT    14
#define WT    14
#define HS    96
#define WS    96
#define NS    (HS*WS)       // 9216
#define NK    (NS+1)        // 9217
#define SMH   (HS-HT+1)     // 83
#define SMW   (WS-WT+1)     // 83
#define NPW   16            // n-values per warp in attn
#define AWRP  4             // warps per attn block
#define DCH   8             // dim-chunks in proto grid
#define DPB   (D_/DCH)      // 96 threads per proto block

__device__ float g_acc[T_][B_][D_];   // per-template masked sums (pre-division)
__device__ float g_cnt[T_][B_];       // per-template counts
__device__ float g_track[B_*NS];
__device__ float g_blurh[B_*NS];      // fully blurred map (v then h)

// ---------------------------------------------------------------------------
// Kernel A: box-masked pooling sums. UNCHANGED from R14 (proven best).
// ---------------------------------------------------------------------------
__global__ void __launch_bounds__(DPB) proto_kernel(const float* __restrict__ patches,
                                                    const float* __restrict__ annos) {
    int b = blockIdx.x, t = blockIdx.y;
    int d = blockIdx.z * DPB + threadIdx.x;

    const float* a = annos + (t * B_ + b) * 4;
    float a0 = a[0], a1 = a[1], a2 = a[2], a3 = a[3];
    int x1 = (int)floorf(a0 * (float)WT);
    int y1 = (int)floorf(a1 * (float)HT);
    int x2 = (int)floorf((a0 + a2) * (float)WT);
    int y2 = (int)floorf((a1 + a3) * (float)HT);

    const float* base = patches + ((size_t)(t * B_ + b)) * NT * D_ + d;
    float s = 0.f;
    int c = 0;
#pragma unroll
    for (int r = 0; r < HT; r++) {
        bool inr = (r >= y1) && (r < y2);
#pragma unroll
        for (int cc = 0; cc < WT; cc++) {
            bool in = inr && (cc >= x1) && (cc < x2);
            float m = in ? 1.0f : 0.0f;
            c += in ? 1 : 0;
            s += m * base[(size_t)(r * WT + cc) * D_];
        }
    }
    g_acc[t][b][d] = s;
    if (blockIdx.z == 0 && threadIdx.x == 0) g_cnt[t][b] = (float)c;
}

// ---------------------------------------------------------------------------
// Kernel B: attn + head-mean -> track. UNCHANGED from R14 (proven best).
// ---------------------------------------------------------------------------
__global__ void __launch_bounds__(32*AWRP) attn_kernel(const float* __restrict__ skey) {
    int b    = blockIdx.y;
    int warp = threadIdx.x >> 5;
    int lane = threadIdx.x & 31;
    int hl   = lane >> 4;     // 0 or 1
    int d4   = lane & 15;     // float4 index within head

    float c0 = g_cnt[0][b] + 1e-6f;
    float c1 = g_cnt[1][b] + 1e-6f;

    float4 pr[6];
#pragma unroll
    for (int j = 0; j < 6; j++) {
        int h = 2 * j + hl;
        float4 q0 = *(const float4*)(&g_acc[0][b][h * HD + d4 * 4]);
        float4 q1 = *(const float4*)(&g_acc[1][b][h * HD + d4 * 4]);
        pr[j].x = 0.5f * (q0.x / c0 + q1.x / c1);
        pr[j].y = 0.5f * (q0.y / c0 + q1.y / c1);
        pr[j].z = 0.5f * (q0.z / c0 + q1.z / c1);
        pr[j].w = 0.5f * (q0.w / c0 + q1.w / c1);
    }

    int n0 = blockIdx.x * (AWRP * NPW) + warp * NPW;
    const float* kb = skey + ((size_t)b * HEADS) * (size_t)NK * HD;

    float acc[NPW];
#pragma unroll
    for (int r = 0; r < NPW; r++) acc[r] = 0.f;

#pragma unroll
    for (int j = 0; j < 6; j++) {
        int h = 2 * j + hl;
        const float4* p = (const float4*)(kb + ((size_t)h * NK + (size_t)(n0 + 1)) * HD) + d4;
#pragma unroll
        for (int r = 0; r < NPW; r++) {
            float4 k = __ldcs(p + r * (HD / 4));
            acc[r] += k.x * pr[j].x + k.y * pr[j].y + k.z * pr[j].z + k.w * pr[j].w;
        }
    }

    const float scale = 0.125f / 12.0f;   // hd^-0.5 / heads
#pragma unroll
    for (int r = 0; r < NPW; r++) {
#pragma unroll
        for (int off = 16; off; off >>= 1)
            acc[r] += __shfl_xor_sync(0xffffffffu, acc[r], off);
    }
    if (lane == 0) {
        float4* tr = (float4*)(g_track + b * NS + n0);
#pragma unroll
        for (int q = 0; q < NPW / 4; q++) {
            tr[q] = make_float4(acc[4 * q + 0] * scale, acc[4 * q + 1] * scale,
                                acc[4 * q + 2] * scale, acc[4 * q + 3] * scale);
        }
    }
}

// ---------------------------------------------------------------------------
// Kernel BL: fully-parallel blur, closed form per output. Each output
// recomputes its 5 vertical-blur taps with the IDENTICAL expression the
// two-pass version used -> bit-identical values, but full-chip parallel
// (1152 blocks) instead of serialized inside 32 post blocks.
// ---------------------------------------------------------------------------
__device__ __forceinline__ int reflect_idx(int i, int n) {
    if (i < 0)  return -i;
    if (i >= n) return 2 * n - 2 - i;
    return i;
}

__device__ __forceinline__ float vblur_at(const float* __restrict__ tr, int y, int x,
                                          float w0, float w1, float w2) {
    float vm2 = tr[reflect_idx(y - 2, HS) * WS + x];
    float vm1 = tr[reflect_idx(y - 1, HS) * WS + x];
    float v0  = tr[y * WS + x];
    float vp1 = tr[reflect_idx(y + 1, HS) * WS + x];
    float vp2 = tr[reflect_idx(y + 2, HS) * WS + x];
    return w2 * vm2 + w1 * vm1 + w0 * v0 + w1 * vp1 + w2 * vp2;
}

__global__ void __launch_bounds__(256) blur_kernel() {
    int b = blockIdx.y;
    int i = blockIdx.x * 256 + threadIdx.x;
    int y = i / WS, x = i - y * WS;

    float k1 = expf(-1.0f / 2.42f);
    float k2 = expf(-4.0f / 2.42f);
    float s  = 1.0f + 2.0f * k1 + 2.0f * k2;
    float w0 = 1.0f / s, w1 = k1 / s, w2 = k2 / s;

    const float* tr = g_track + b * NS;
    float vm2 = vblur_at(tr, y, reflect_idx(x - 2, WS), w0, w1, w2);
    float vm1 = vblur_at(tr, y, reflect_idx(x - 1, WS), w0, w1, w2);
    float v0  = vblur_at(tr, y, x,                      w0, w1, w2);
    float vp1 = vblur_at(tr, y, reflect_idx(x + 1, WS), w0, w1, w2);
    float vp2 = vblur_at(tr, y, reflect_idx(x + 2, WS), w0, w1, w2);
    g_blurh[b * NS + i] = w2 * vm2 + w1 * vm1 + w0 * v0 + w1 * vp1 + w2 * vp2;
}

// ---------------------------------------------------------------------------
// Kernel C: per-batch post starting at softmax. All reduction trees, strided
// loops, cumsums, and tie-break EXACTLY as the passing R14 kernel (the blur
// values it loads are bit-identical to what it used to compute in-place).
// ---------------------------------------------------------------------------
__global__ void __launch_bounds__(256) post_kernel(float* __restrict__ out) {
    __shared__ float sA[NS];
    __shared__ float red[256];
    __shared__ int   redi[256];

    int b   = blockIdx.x;
    int tid = threadIdx.x;

    // load blurred map (elementwise copy, vectorized — order-insensitive)
    const float4* src = (const float4*)(g_blurh + b * NS);
    float4* dst4 = (float4*)sA;
    for (int i = tid; i < NS / 4; i += 256) dst4[i] = src[i];
    __syncthreads();

    // softmax over 9216 (identical strided order + tree as before)
    float m = -3.402823e38f;
    for (int i = tid; i < NS; i += 256) m = fmaxf(m, sA[i]);
    red[tid] = m; __syncthreads();
    for (int off = 128; off; off >>= 1) {
        if (tid < off) red[tid] = fmaxf(red[tid], red[tid + off]);
        __syncthreads();
    }
    m = red[0]; __syncthreads();

    float sum = 0.f;
    for (int i = tid; i < NS; i += 256) { float e = expf(sA[i] - m); sA[i] = e; sum += e; }
    red[tid] = sum; __syncthreads();
    for (int off = 128; off; off >>= 1) {
        if (tid < off) red[tid] += red[tid + off];
        __syncthreads();
    }
    float inv = 1.0f / red[0]; __syncthreads();

    // prob normalize + write (elementwise, vectorized — bits per element same)
    float4* probOut4 = (float4*)(out + 5 * B_ + (size_t)b * NS);
    for (int i = tid; i < NS / 4; i += 256) {
        float4 e = dst4[i];
        float4 p = make_float4(e.x * inv, e.y * inv, e.z * inv, e.w * inv);
        dst4[i] = p;
        probOut4[i] = p;
    }
    __syncthreads();

    // integral image: row cumsum then column cumsum (matches jnp order)
    if (tid < HS) {
        float c = 0.f;
        float* r = sA + tid * WS;
        for (int x = 0; x < WS; x++) { c += r[x]; r[x] = c; }
    }
    __syncthreads();
    if (tid < WS) {
        float c = 0.f;
        for (int y = 0; y < HS; y++) { c += sA[y * WS + tid]; sA[y * WS + tid] = c; }
    }
    __syncthreads();

    // 14x14 window sums over 83x83 positions, first-occurrence argmax
    float bv = -3.402823e38f;
    int   bi = 0x7fffffff;
    for (int i = tid; i < SMH * SMW; i += 256) {
        int y = i / SMW, x = i - y * SMW;
        float Dv = sA[(y + HT - 1) * WS + (x + WT - 1)];
        float Bv = (y > 0)          ? sA[(y - 1) * WS + (x + WT - 1)] : 0.0f;
        float Cv = (x > 0)          ? sA[(y + HT - 1) * WS + (x - 1)] : 0.0f;
        float Av = (y > 0 && x > 0) ? sA[(y - 1) * WS + (x - 1)]      : 0.0f;
        float v = Dv - Bv - Cv + Av;
        if (v > bv || (v == bv && i < bi)) { bv = v; bi = i; }
    }
    red[tid] = bv; redi[tid] = bi; __syncthreads();
    for (int off = 128; off; off >>= 1) {
        if (tid < off) {
            float ov = red[tid + off]; int oi = redi[tid + off];
            if (ov > red[tid] || (ov == red[tid] && oi < redi[tid])) {
                red[tid] = ov; redi[tid] = oi;
            }
        }
        __syncthreads();
    }
    if (tid == 0) {
        int idx = redi[0];
        out[0 * B_ + b] = (float)(idx % SMW);   // best_x
        out[1 * B_ + b] = (float)(idx / SMW);   // best_y
        out[2 * B_ + b] = (float)WT;            // win_w
        out[3 * B_ + b] = (float)HT;            // win_h
        out[4 * B_ + b] = red[0];               // confidence
    }
}

// ---------------------------------------------------------------------------
extern "C" void kernel_launch(void* const* d_in, const int* in_sizes, int n_in,
                              void* d_out, int out_size) {
    const float* patches = (const float*)d_in[0];
    const float* annos   = (const float*)d_in[1];
    const float* skey    = (const float*)d_in[2];
    float* out = (float*)d_out;

    proto_kernel<<<dim3(B_, T_, DCH), DPB>>>(patches, annos);

    dim3 gAttn(NS / (AWRP * NPW), B_);   // 144 x 32
    attn_kernel<<<gAttn, 32 * AWRP>>>(skey);

    dim3 gBlur(NS / 256, B_);            // 36 x 32
    blur_kernel<<<gBlur, 256>>>();

    post_kernel<<<B_, 256>>>(out);
}